// round 2
// baseline (speedup 1.0000x reference)
#include <cuda_runtime.h>

#define NB 64
#define NN 512
#define ND 128
#define TB 128        // output tile (TB x TB)
#define KC 64         // K chunk
#define AS_STRIDE (KC + 4)   // 68, i-major A tile row stride (floats)
#define BS_STRIDE (TB + 4)   // 132, k-major B tile row stride (floats)
#define SMEM_FLOATS (TB*AS_STRIDE + KC*BS_STRIDE + 6*TB)

// scratch: 1/max(||row||, 1e-8) for all B*N rows
__device__ float g_rnorm[NB * NN];

__global__ void rnorm_kernel(const float* __restrict__ fea) {
    int row  = blockIdx.x * 8 + (threadIdx.x >> 5);
    int lane = threadIdx.x & 31;
    const float4* p = reinterpret_cast<const float4*>(fea + (size_t)row * ND);
    float4 v = p[lane];                       // 32 lanes x 4 floats = 128
    float s = v.x*v.x + v.y*v.y + v.z*v.z + v.w*v.w;
    #pragma unroll
    for (int o = 16; o > 0; o >>= 1) s += __shfl_xor_sync(0xffffffffu, s, o);
    if (lane == 0) g_rnorm[row] = 1.0f / fmaxf(sqrtf(s), 1e-8f);
}

__global__ __launch_bounds__(256, 2)
void adj_kernel(const float* __restrict__ fea, const float* __restrict__ coord,
                float* __restrict__ out) {
    extern __shared__ float sm[];
    float* As    = sm;                          // [TB][AS_STRIDE] i-major
    float* Bs    = As + TB * AS_STRIDE;         // [KC][BS_STRIDE] k-major (transposed)
    float* rni_s = Bs + KC * BS_STRIDE;
    float* rnj_s = rni_s + TB;
    float* cxi_s = rnj_s + TB;
    float* cyi_s = cxi_s + TB;
    float* cxj_s = cyi_s + TB;
    float* cyj_s = cxj_s + TB;

    const int tid = threadIdx.x;
    const int blk = blockIdx.x;
    const int b = blk / 10;
    const int t = blk % 10;
    // upper-triangle tile pairs (bi <= bj) among 4x4 tiles
    const unsigned char bi_t[10] = {0,0,0,0,1,1,1,2,2,3};
    const unsigned char bj_t[10] = {0,1,2,3,1,2,3,2,3,3};
    const int bi = bi_t[t], bj = bj_t[t];
    const int iBase = bi * TB, jBase = bj * TB;
    const bool diag = (bi == bj);

    const float* Ai = fea + ((size_t)b * NN + iBase) * ND;
    const float* Aj = fea + ((size_t)b * NN + jBase) * ND;

    // stage coords + rnorms for this tile pair
    if (tid < 128) {
        int i = tid;
        rni_s[i] = g_rnorm[b * NN + iBase + i];
        float2 c = reinterpret_cast<const float2*>(coord)[(size_t)b * NN + iBase + i];
        cxi_s[i] = c.x; cyi_s[i] = c.y;
    } else {
        int j = tid - 128;
        rnj_s[j] = g_rnorm[b * NN + jBase + j];
        float2 c = reinterpret_cast<const float2*>(coord)[(size_t)b * NN + jBase + j];
        cxj_s[j] = c.x; cyj_s[j] = c.y;
    }

    float acc[8][8];
    #pragma unroll
    for (int ii = 0; ii < 8; ii++)
        #pragma unroll
        for (int jj = 0; jj < 8; jj++) acc[ii][jj] = 0.0f;

    const int tx = tid & 15;   // j dim, 16 threads
    const int ty = tid >> 4;   // i dim, 16 threads

    for (int kb = 0; kb < ND; kb += KC) {
        __syncthreads();   // protect smem reuse across chunks (and coord staging)
        // A tile: 128 rows x 64 floats, i-major, coalesced float4 in+out
        #pragma unroll
        for (int it = 0; it < 8; it++) {
            int idx = tid + it * 256;
            int r = idx >> 4, c4 = (idx & 15) * 4;
            float4 v = *reinterpret_cast<const float4*>(Ai + (size_t)r * ND + kb + c4);
            *reinterpret_cast<float4*>(&As[r * AS_STRIDE + c4]) = v;
        }
        // B tile: transposed to k-major; gmem reads 16B-scattered (2x sector),
        // smem stores conflict-free (consecutive r per warp)
        #pragma unroll
        for (int it = 0; it < 8; it++) {
            int idx = tid + it * 256;
            int r = idx & 127, c4 = (idx >> 7) * 4;
            float4 v = *reinterpret_cast<const float4*>(Aj + (size_t)r * ND + kb + c4);
            Bs[(c4 + 0) * BS_STRIDE + r] = v.x;
            Bs[(c4 + 1) * BS_STRIDE + r] = v.y;
            Bs[(c4 + 2) * BS_STRIDE + r] = v.z;
            Bs[(c4 + 3) * BS_STRIDE + r] = v.w;
        }
        __syncthreads();

        #pragma unroll 4
        for (int k = 0; k < KC; k++) {
            float4 b0 = *reinterpret_cast<const float4*>(&Bs[k * BS_STRIDE + tx * 8]);
            float4 b1 = *reinterpret_cast<const float4*>(&Bs[k * BS_STRIDE + tx * 8 + 4]);
            float bv[8] = {b0.x, b0.y, b0.z, b0.w, b1.x, b1.y, b1.z, b1.w};
            float av[8];
            #pragma unroll
            for (int ii = 0; ii < 8; ii++)
                av[ii] = As[(ty * 8 + ii) * AS_STRIDE + k];  // broadcast across tx
            #pragma unroll
            for (int ii = 0; ii < 8; ii++)
                #pragma unroll
                for (int jj = 0; jj < 8; jj++)
                    acc[ii][jj] = fmaf(av[ii], bv[jj], acc[ii][jj]);
        }
    }

    float* outA = out;
    float* outS = out + (size_t)NB * NN * NN;
    const size_t base = (size_t)b * NN * NN;
    const int gi0 = iBase + ty * 8;
    const int gj0 = jBase + tx * 8;

    // direct tile (i rows, j cols) — fully coalesced float4
    #pragma unroll
    for (int ii = 0; ii < 8; ii++) {
        const int gi = gi0 + ii;
        const float rni = rni_s[ty * 8 + ii];
        const float cx  = cxi_s[ty * 8 + ii];
        const float cy  = cyi_s[ty * 8 + ii];
        float av[8], sv[8];
        #pragma unroll
        for (int jj = 0; jj < 8; jj++) {
            const int lj = tx * 8 + jj;
            float dx = cx - cxj_s[lj], dy = cy - cyj_s[lj];
            float dist = sqrtf(dx * dx + dy * dy);
            float cosv = acc[ii][jj] * rni * rnj_s[lj];
            bool same = (gi == (gj0 + jj));
            av[jj] = same ? 0.0f : cosv * __expf(-dist);
            sv[jj] = (!same && dist < 1.0f) ? 1.0f : 0.0f;
        }
        size_t ro = base + (size_t)gi * NN + gj0;
        *reinterpret_cast<float4*>(outA + ro)     = make_float4(av[0], av[1], av[2], av[3]);
        *reinterpret_cast<float4*>(outA + ro + 4) = make_float4(av[4], av[5], av[6], av[7]);
        *reinterpret_cast<float4*>(outS + ro)     = make_float4(sv[0], sv[1], sv[2], sv[3]);
        *reinterpret_cast<float4*>(outS + ro + 4) = make_float4(sv[4], sv[5], sv[6], sv[7]);
    }

    // mirror tile (j rows, i cols) — values identical by symmetry; recompute
    // epilogue per column to keep register pressure low, writes coalesced
    if (!diag) {
        #pragma unroll
        for (int jj = 0; jj < 8; jj++) {
            const int gj = gj0 + jj;
            const int lj = tx * 8 + jj;
            const float rnj = rnj_s[lj];
            const float cx  = cxj_s[lj];
            const float cy  = cyj_s[lj];
            float av[8], sv[8];
            #pragma unroll
            for (int ii = 0; ii < 8; ii++) {
                const int li = ty * 8 + ii;
                float dx = cx - cxi_s[li], dy = cy - cyi_s[li];
                float dist = sqrtf(dx * dx + dy * dy);
                float cosv = acc[ii][jj] * rni_s[li] * rnj;
                av[ii] = cosv * __expf(-dist);       // off-diag block: gi != gj always
                sv[ii] = (dist < 1.0f) ? 1.0f : 0.0f;
            }
            size_t ro = base + (size_t)gj * NN + gi0;
            *reinterpret_cast<float4*>(outA + ro)     = make_float4(av[0], av[1], av[2], av[3]);
            *reinterpret_cast<float4*>(outA + ro + 4) = make_float4(av[4], av[5], av[6], av[7]);
            *reinterpret_cast<float4*>(outS + ro)     = make_float4(sv[0], sv[1], sv[2], sv[3]);
            *reinterpret_cast<float4*>(outS + ro + 4) = make_float4(sv[4], sv[5], sv[6], sv[7]);
        }
    }
}

extern "C" void kernel_launch(void* const* d_in, const int* in_sizes, int n_in,
                              void* d_out, int out_size) {
    (void)in_sizes; (void)n_in; (void)out_size;
    const float* fea   = (const float*)d_in[0];
    const float* coord = (const float*)d_in[1];
    float* out = (float*)d_out;

    rnorm_kernel<<<NB * NN / 8, 256>>>(fea);

    const int smem_bytes = SMEM_FLOATS * (int)sizeof(float);   // 71680 B
    cudaFuncSetAttribute(adj_kernel, cudaFuncAttributeMaxDynamicSharedMemorySize, smem_bytes);
    adj_kernel<<<NB * 10, 256, smem_bytes>>>(fea, coord, out);
}

// round 5
// speedup vs baseline: 1.9709x; 1.9709x over previous
#include <cuda_runtime.h>
#include <cuda_bf16.h>
#include <cstdint>

#define NB 64
#define NN 512
#define ND 128
#define TB 128

// pre-normalized features, bf16 hi/lo planes
__device__ uint4 g_hi[(NB * NN * ND * 2) / 16];
__device__ uint4 g_lo[(NB * NN * ND * 2) / 16];

__device__ __forceinline__ uint32_t smem_u32(const void* p) {
    uint32_t a;
    asm("{ .reg .u64 t; cvta.to.shared.u64 t, %1; cvt.u32.u64 %0, t; }" : "=r"(a) : "l"(p));
    return a;
}

#define LDSM_X4(r, addr)                                                                  \
    asm volatile("ldmatrix.sync.aligned.m8n8.x4.shared.b16 {%0,%1,%2,%3}, [%4];"          \
                 : "=r"((r)[0]), "=r"((r)[1]), "=r"((r)[2]), "=r"((r)[3]) : "r"(addr))

__device__ __forceinline__ void mma16816(float* c, uint32_t a0, uint32_t a1, uint32_t a2,
                                         uint32_t a3, uint32_t b0, uint32_t b1) {
    asm volatile("mma.sync.aligned.m16n8k16.row.col.f32.bf16.bf16.f32 "
                 "{%0,%1,%2,%3}, {%4,%5,%6,%7}, {%8,%9}, {%0,%1,%2,%3};"
                 : "+f"(c[0]), "+f"(c[1]), "+f"(c[2]), "+f"(c[3])
                 : "r"(a0), "r"(a1), "r"(a2), "r"(a3), "r"(b0), "r"(b1));
}

// smem layout (bytes). Row stride 144 B (9*16B) -> conflict-free ldmatrix.
#define SMA 144
#define OFF_AHI 0
#define OFF_ALO 18432
#define OFF_BHI 36864
#define OFF_BLO 55296
#define OFF_AVT 0            // reuses operand region after MMA (67584 <= 73728)
#define OFF_CI  73728
#define OFF_CJ  74752
#define SMEM_TOTAL 75776
#define AVT_S 132

// ---------- prep: normalize rows, split to bf16 hi/lo ----------
__global__ void prep_kernel(const float* __restrict__ fea) {
    int row  = blockIdx.x * 8 + (threadIdx.x >> 5);
    int lane = threadIdx.x & 31;
    float4 v = reinterpret_cast<const float4*>(fea + (size_t)row * ND)[lane];
    float s = v.x * v.x + v.y * v.y + v.z * v.z + v.w * v.w;
    #pragma unroll
    for (int o = 16; o > 0; o >>= 1) s += __shfl_xor_sync(0xffffffffu, s, o);
    float rn = 1.0f / fmaxf(sqrtf(s), 1e-8f);
    float x0 = v.x * rn, x1 = v.y * rn, x2 = v.z * rn, x3 = v.w * rn;
    __nv_bfloat16 h0 = __float2bfloat16(x0), h1 = __float2bfloat16(x1);
    __nv_bfloat16 h2 = __float2bfloat16(x2), h3 = __float2bfloat16(x3);
    __nv_bfloat16 l0 = __float2bfloat16(x0 - __bfloat162float(h0));
    __nv_bfloat16 l1 = __float2bfloat16(x1 - __bfloat162float(h1));
    __nv_bfloat16 l2 = __float2bfloat16(x2 - __bfloat162float(h2));
    __nv_bfloat16 l3 = __float2bfloat16(x3 - __bfloat162float(h3));
    uint2 hv, lv;
    hv.x = (uint32_t)__bfloat16_as_ushort(h0) | ((uint32_t)__bfloat16_as_ushort(h1) << 16);
    hv.y = (uint32_t)__bfloat16_as_ushort(h2) | ((uint32_t)__bfloat16_as_ushort(h3) << 16);
    lv.x = (uint32_t)__bfloat16_as_ushort(l0) | ((uint32_t)__bfloat16_as_ushort(l1) << 16);
    lv.y = (uint32_t)__bfloat16_as_ushort(l2) | ((uint32_t)__bfloat16_as_ushort(l3) << 16);
    reinterpret_cast<uint2*>(g_hi)[(size_t)row * 32 + lane] = hv;
    reinterpret_cast<uint2*>(g_lo)[(size_t)row * 32 + lane] = lv;
}

// ---------- main fused kernel: HMMA tile-pair ----------
__global__ __launch_bounds__(512)
void adj_mma_kernel(const float* __restrict__ coord, float* __restrict__ out) {
    extern __shared__ char sm[];
    const uint32_t smb = smem_u32(sm);
    const int tid  = threadIdx.x;
    const int wid  = tid >> 5;
    const int lane = tid & 31;
    const int wy = wid >> 2;          // 0..3, m dim
    const int wx = wid & 3;           // 0..3, n dim

    const int blk = blockIdx.x;
    const int b = blk / 10;
    const int t = blk % 10;
    const unsigned char bi_t[10] = {0,0,0,0,1,1,1,2,2,3};
    const unsigned char bj_t[10] = {0,1,2,3,1,2,3,2,3,3};
    const int iBase = bi_t[t] * TB, jBase = bj_t[t] * TB;
    const bool diag = (iBase == jBase);

    // stage coords
    {
        float2* ci2 = reinterpret_cast<float2*>(sm + OFF_CI);
        float2* cj2 = reinterpret_cast<float2*>(sm + OFF_CJ);
        if (tid < 128)
            ci2[tid] = reinterpret_cast<const float2*>(coord)[(size_t)b * NN + iBase + tid];
        else if (tid < 256)
            cj2[tid - 128] = reinterpret_cast<const float2*>(coord)[(size_t)b * NN + jBase + (tid - 128)];
    }

    float acc[2][4][4];
    #pragma unroll
    for (int mt = 0; mt < 2; mt++)
        #pragma unroll
        for (int nt = 0; nt < 4; nt++)
            #pragma unroll
            for (int q = 0; q < 4; q++) acc[mt][nt][q] = 0.0f;

    const uint32_t aRowH = smb + OFF_AHI + (uint32_t)(wy * 32 + lane) * SMA;
    const uint32_t aRowL = aRowH + (OFF_ALO - OFF_AHI);
    const uint32_t bRowH = smb + OFF_BHI + (uint32_t)(wx * 32 + lane) * SMA;
    const uint32_t bRowL = bRowH + (OFF_BLO - OFF_BHI);

    #pragma unroll
    for (int kc = 0; kc < 2; kc++) {
        __syncthreads();
        // load 4 tiles: 128 rows x 64 bf16 each (this K chunk)
        {
            const uint32_t tileOff[4] = {OFF_AHI, OFF_ALO, OFF_BHI, OFF_BLO};
            #pragma unroll
            for (int it = 0; it < 8; it++) {
                int idx = tid + it * 512;
                int tile = idx >> 10;           // 1024 uint4 per tile
                int e = idx & 1023;
                int row = e >> 3;
                int c8 = (e & 7) * 8;
                int rowsBase = (tile < 2) ? iBase : jBase;
                const uint4* src = (tile & 1) ? g_lo : g_hi;
                uint4 v = src[((size_t)(b * NN + rowsBase + row) * ND + kc * 64 + c8) >> 3];
                *reinterpret_cast<uint4*>(sm + tileOff[tile] + row * SMA + c8 * 2) = v;
            }
        }
        __syncthreads();

        #pragma unroll
        for (int ks = 0; ks < 4; ks++) {
            const uint32_t co = (uint32_t)(ks * 32);       // kk*2 bytes
            uint32_t ah1[4], ah2[4], al1[4], al2[4];
            uint32_t bh1[4], bh2[4], bl1[4], bl2[4];
            LDSM_X4(ah1, aRowH + co);
            LDSM_X4(ah2, aRowH + co + 16);
            LDSM_X4(bh1, bRowH + co);
            LDSM_X4(bh2, bRowH + co + 16);
            LDSM_X4(al1, aRowL + co);
            LDSM_X4(al2, aRowL + co + 16);
            LDSM_X4(bl1, bRowL + co);
            LDSM_X4(bl2, bRowL + co + 16);
            #pragma unroll
            for (int mt = 0; mt < 2; mt++) {
                #pragma unroll
                for (int nt = 0; nt < 4; nt++) {
                    float* c = acc[mt][nt];
                    mma16816(c, ah1[mt*2], ah1[mt*2+1], ah2[mt*2], ah2[mt*2+1], bh1[nt], bh2[nt]);
                    mma16816(c, ah1[mt*2], ah1[mt*2+1], ah2[mt*2], ah2[mt*2+1], bl1[nt], bl2[nt]);
                    mma16816(c, al1[mt*2], al1[mt*2+1], al2[mt*2], al2[mt*2+1], bh1[nt], bh2[nt]);
                }
            }
        }
    }

    __syncthreads();   // all warps done with operand smem; avt reuses it

    // epilogue: direct-tile stores from fragments + transposed staging for mirror
    {
        const float2* ci2 = reinterpret_cast<const float2*>(sm + OFF_CI);
        const float2* cj2 = reinterpret_cast<const float2*>(sm + OFF_CJ);
        float* avt = reinterpret_cast<float*>(sm + OFF_AVT);
        float* outA = out;
        float* outS = out + (size_t)NB * NN * NN;
        const size_t base = (size_t)b * NN * NN;
        const int g = lane >> 2, q = lane & 3;

        #pragma unroll
        for (int mt = 0; mt < 2; mt++) {
            #pragma unroll
            for (int nt = 0; nt < 4; nt++) {
                const float* c = acc[mt][nt];
                const int lj = wx * 32 + nt * 8 + q * 2;
                const float2 cj0 = cj2[lj], cj1 = cj2[lj + 1];
                #pragma unroll
                for (int h = 0; h < 2; h++) {
                    const int li = wy * 32 + mt * 16 + g + h * 8;
                    const float2 ci = ci2[li];
                    float dx0 = ci.x - cj0.x, dy0 = ci.y - cj0.y;
                    float dx1 = ci.x - cj1.x, dy1 = ci.y - cj1.y;
                    float d20 = dx0 * dx0 + dy0 * dy0;
                    float d21 = dx1 * dx1 + dy1 * dy1;
                    bool s0 = diag && (li == lj);
                    bool s1 = diag && (li == lj + 1);
                    float av0 = s0 ? 0.0f : c[h * 2 + 0] * __expf(-sqrtf(d20));
                    float av1 = s1 ? 0.0f : c[h * 2 + 1] * __expf(-sqrtf(d21));
                    float sv0 = (!s0 && d20 < 1.0f) ? 1.0f : 0.0f;
                    float sv1 = (!s1 && d21 < 1.0f) ? 1.0f : 0.0f;
                    size_t ro = base + (size_t)(iBase + li) * NN + jBase + lj;
                    *reinterpret_cast<float2*>(outA + ro) = make_float2(av0, av1);
                    *reinterpret_cast<float2*>(outS + ro) = make_float2(sv0, sv1);
                    if (!diag) {
                        avt[(size_t)lj * AVT_S + li]       = av0;
                        avt[(size_t)(lj + 1) * AVT_S + li] = av1;
                    }
                }
            }
        }
    }

    // mirror pass
    if (!diag) {
        __syncthreads();
        const float* avt = reinterpret_cast<const float*>(sm + OFF_AVT);
        const float2* cj2 = reinterpret_cast<const float2*>(sm + OFF_CJ);
        const float4* ci4 = reinterpret_cast<const float4*>(sm + OFF_CI);
        float* outA = out;
        float* outS = out + (size_t)NB * NN * NN;
        const size_t base = (size_t)b * NN * NN;

        #pragma unroll
        for (int it = 0; it < 8; it++) {
            const int r = wid * 8 + it;     // local j row
            float4 av4 = *reinterpret_cast<const float4*>(avt + (size_t)r * AVT_S + lane * 4);
            float2 cj = cj2[r];
            float4 p0 = ci4[lane * 2], p1 = ci4[lane * 2 + 1];
            float d0x = cj.x - p0.x, d0y = cj.y - p0.y;
            float d1x = cj.x - p0.z, d1y = cj.y - p0.w;
            float d2x = cj.x - p1.x, d2y = cj.y - p1.y;
            float d3x = cj.x - p1.z, d3y = cj.y - p1.w;
            float4 sv4;
            sv4.x = (d0x * d0x + d0y * d0y < 1.0f) ? 1.0f : 0.0f;
            sv4.y = (d1x * d1x + d1y * d1y < 1.0f) ? 1.0f : 0.0f;
            sv4.z = (d2x * d2x + d2y * d2y < 1.0f) ? 1.0f : 0.0f;
            sv4.w = (d3x * d3x + d3y * d3y < 1.0f) ? 1.0f : 0.0f;
            size_t ro = base + (size_t)(jBase + r) * NN + iBase + lane * 4;
            *reinterpret_cast<float4*>(outA + ro) = av4;
            *reinterpret_cast<float4*>(outS + ro) = sv4;
        }
    }
}

extern "C" void kernel_launch(void* const* d_in, const int* in_sizes, int n_in,
                              void* d_out, int out_size) {
    (void)in_sizes; (void)n_in; (void)out_size;
    const float* fea   = (const float*)d_in[0];
    const float* coord = (const float*)d_in[1];
    float* out = (float*)d_out;

    prep_kernel<<<NB * NN / 8, 256>>>(fea);

    cudaFuncSetAttribute(adj_mma_kernel, cudaFuncAttributeMaxDynamicSharedMemorySize, SMEM_TOTAL);
    adj_mma_kernel<<<NB * 10, 512, SMEM_TOTAL>>>(coord, out);
}

// round 6
// speedup vs baseline: 1.9787x; 1.0039x over previous
#include <cuda_runtime.h>
#include <cuda_bf16.h>
#include <cstdint>

#define NB 64
#define NN 512
#define ND 128
#define TB 128

// pre-normalized features, bf16 hi/lo planes
__device__ uint4 g_hi[(NB * NN * ND * 2) / 16];
__device__ uint4 g_lo[(NB * NN * ND * 2) / 16];

__device__ __forceinline__ uint32_t smem_u32(const void* p) {
    uint32_t a;
    asm("{ .reg .u64 t; cvta.to.shared.u64 t, %1; cvt.u32.u64 %0, t; }" : "=r"(a) : "l"(p));
    return a;
}

#define LDSM_X4(r, addr)                                                                  \
    asm volatile("ldmatrix.sync.aligned.m8n8.x4.shared.b16 {%0,%1,%2,%3}, [%4];"          \
                 : "=r"((r)[0]), "=r"((r)[1]), "=r"((r)[2]), "=r"((r)[3]) : "r"(addr))

#define CP_ASYNC16(sa, gp)                                                                \
    asm volatile("cp.async.cg.shared.global [%0], [%1], 16;" :: "r"(sa), "l"(gp) : "memory")
#define CP_COMMIT() asm volatile("cp.async.commit_group;" ::: "memory")
#define CP_WAIT(n)  asm volatile("cp.async.wait_group %0;" :: "n"(n) : "memory")

__device__ __forceinline__ void mma16816(float* c, uint32_t a0, uint32_t a1, uint32_t a2,
                                         uint32_t a3, uint32_t b0, uint32_t b1) {
    asm volatile("mma.sync.aligned.m16n8k16.row.col.f32.bf16.bf16.f32 "
                 "{%0,%1,%2,%3}, {%4,%5,%6,%7}, {%8,%9}, {%0,%1,%2,%3};"
                 : "+f"(c[0]), "+f"(c[1]), "+f"(c[2]), "+f"(c[3])
                 : "r"(a0), "r"(a1), "r"(a2), "r"(a3), "r"(b0), "r"(b1));
}

// smem layout (bytes). Row stride 144 B (9*16B) -> conflict-free ldmatrix.
#define SMA 144
#define PLANE 18432          // 128 * SMA
#define CHUNK 73728          // 4 planes
#define OFF_AVT 0            // reuses chunk-0 operand region after MMA (67584 < 73728)
#define OFF_CI  147456       // 128 float2
#define OFF_CJ  148480
#define SMEM_TOTAL 149504
#define AVT_S 132

// ---------- prep: normalize rows, split to bf16 hi/lo ----------
__global__ void prep_kernel(const float* __restrict__ fea) {
    int row  = blockIdx.x * 8 + (threadIdx.x >> 5);
    int lane = threadIdx.x & 31;
    float4 v = reinterpret_cast<const float4*>(fea + (size_t)row * ND)[lane];
    float s = v.x * v.x + v.y * v.y + v.z * v.z + v.w * v.w;
    #pragma unroll
    for (int o = 16; o > 0; o >>= 1) s += __shfl_xor_sync(0xffffffffu, s, o);
    float rn = 1.0f / fmaxf(sqrtf(s), 1e-8f);
    float x0 = v.x * rn, x1 = v.y * rn, x2 = v.z * rn, x3 = v.w * rn;
    __nv_bfloat16 h0 = __float2bfloat16(x0), h1 = __float2bfloat16(x1);
    __nv_bfloat16 h2 = __float2bfloat16(x2), h3 = __float2bfloat16(x3);
    __nv_bfloat16 l0 = __float2bfloat16(x0 - __bfloat162float(h0));
    __nv_bfloat16 l1 = __float2bfloat16(x1 - __bfloat162float(h1));
    __nv_bfloat16 l2 = __float2bfloat16(x2 - __bfloat162float(h2));
    __nv_bfloat16 l3 = __float2bfloat16(x3 - __bfloat162float(h3));
    uint2 hv, lv;
    hv.x = (uint32_t)__bfloat16_as_ushort(h0) | ((uint32_t)__bfloat16_as_ushort(h1) << 16);
    hv.y = (uint32_t)__bfloat16_as_ushort(h2) | ((uint32_t)__bfloat16_as_ushort(h3) << 16);
    lv.x = (uint32_t)__bfloat16_as_ushort(l0) | ((uint32_t)__bfloat16_as_ushort(l1) << 16);
    lv.y = (uint32_t)__bfloat16_as_ushort(l2) | ((uint32_t)__bfloat16_as_ushort(l3) << 16);
    reinterpret_cast<uint2*>(g_hi)[(size_t)row * 32 + lane] = hv;
    reinterpret_cast<uint2*>(g_lo)[(size_t)row * 32 + lane] = lv;
}

// ---------- main fused kernel: HMMA tile-pair, cp.async double-buffered ----------
__global__ __launch_bounds__(512)
void adj_mma_kernel(const float* __restrict__ coord, float* __restrict__ out) {
    extern __shared__ char sm[];
    const uint32_t smb = smem_u32(sm);
    const int tid  = threadIdx.x;
    const int wid  = tid >> 5;
    const int lane = tid & 31;
    const int wy = wid >> 2;          // 0..3, m dim
    const int wx = wid & 3;           // 0..3, n dim

    const int blk = blockIdx.x;
    const int b = blk / 10;
    const int t = blk % 10;
    const unsigned char bi_t[10] = {0,0,0,0,1,1,1,2,2,3};
    const unsigned char bj_t[10] = {0,1,2,3,1,2,3,2,3,3};
    const int iBase = bi_t[t] * TB, jBase = bj_t[t] * TB;
    const bool diag = (iBase == jBase);

    // issue both K-chunks' tile loads as async groups (register-free)
    #pragma unroll
    for (int kc = 0; kc < 2; kc++) {
        const uint32_t chBase = smb + (uint32_t)kc * CHUNK;
        #pragma unroll
        for (int it = 0; it < 8; it++) {
            int idx = tid + it * 512;
            int tile = idx >> 10;           // 1024 16B-elements per tile
            int e = idx & 1023;
            int row = e >> 3;
            int c8 = (e & 7) * 8;           // bf16 column within chunk
            int rowsBase = (tile < 2) ? iBase : jBase;
            const uint4* src = (tile & 1) ? g_lo : g_hi;
            const uint4* gp = &src[((size_t)(b * NN + rowsBase + row) * ND + kc * 64 + c8) >> 3];
            uint32_t sa = chBase + (uint32_t)(tile * PLANE + row * SMA + c8 * 2);
            CP_ASYNC16(sa, gp);
        }
        CP_COMMIT();
    }

    // stage coords while loads stream
    {
        float2* ci2 = reinterpret_cast<float2*>(sm + OFF_CI);
        float2* cj2 = reinterpret_cast<float2*>(sm + OFF_CJ);
        if (tid < 128)
            ci2[tid] = reinterpret_cast<const float2*>(coord)[(size_t)b * NN + iBase + tid];
        else if (tid < 256)
            cj2[tid - 128] = reinterpret_cast<const float2*>(coord)[(size_t)b * NN + jBase + (tid - 128)];
    }

    float acc[2][4][4];
    #pragma unroll
    for (int mt = 0; mt < 2; mt++)
        #pragma unroll
        for (int nt = 0; nt < 4; nt++)
            #pragma unroll
            for (int q = 0; q < 4; q++) acc[mt][nt][q] = 0.0f;

    const uint32_t aRow0 = smb + (uint32_t)((wy * 32 + lane) * SMA);
    const uint32_t bRow0 = smb + (uint32_t)(2 * PLANE + (wx * 32 + lane) * SMA);

    CP_WAIT(1);               // chunk 0 resident
    __syncthreads();

    #pragma unroll
    for (int kc = 0; kc < 2; kc++) {
        const uint32_t chO = (uint32_t)kc * CHUNK;
        const uint32_t aRowH = aRow0 + chO;
        const uint32_t aRowL = aRowH + PLANE;
        const uint32_t bRowH = bRow0 + chO;
        const uint32_t bRowL = bRowH + PLANE;

        #pragma unroll
        for (int ks = 0; ks < 4; ks++) {
            const uint32_t co = (uint32_t)(ks * 32);
            uint32_t ah1[4], ah2[4], al1[4], al2[4];
            uint32_t bh1[4], bh2[4], bl1[4], bl2[4];
            LDSM_X4(ah1, aRowH + co);
            LDSM_X4(ah2, aRowH + co + 16);
            LDSM_X4(bh1, bRowH + co);
            LDSM_X4(bh2, bRowH + co + 16);
            LDSM_X4(al1, aRowL + co);
            LDSM_X4(al2, aRowL + co + 16);
            LDSM_X4(bl1, bRowL + co);
            LDSM_X4(bl2, bRowL + co + 16);
            #pragma unroll
            for (int mt = 0; mt < 2; mt++) {
                #pragma unroll
                for (int nt = 0; nt < 4; nt++) {
                    float* c = acc[mt][nt];
                    mma16816(c, ah1[mt*2], ah1[mt*2+1], ah2[mt*2], ah2[mt*2+1], bh1[nt], bh2[nt]);
                    mma16816(c, ah1[mt*2], ah1[mt*2+1], ah2[mt*2], ah2[mt*2+1], bl1[nt], bl2[nt]);
                    mma16816(c, al1[mt*2], al1[mt*2+1], al2[mt*2], al2[mt*2+1], bh1[nt], bh2[nt]);
                }
            }
        }
        if (kc == 0) {
            CP_WAIT(0);       // chunk 1 resident
            __syncthreads();
        }
    }

    __syncthreads();   // all warps done with operand smem; avt reuses chunk-0 region

    // epilogue: direct-tile stores from fragments + transposed staging for mirror
    {
        const float2* ci2 = reinterpret_cast<const float2*>(sm + OFF_CI);
        const float2* cj2 = reinterpret_cast<const float2*>(sm + OFF_CJ);
        float* avt = reinterpret_cast<float*>(sm + OFF_AVT);
        float* outA = out;
        float* outS = out + (size_t)NB * NN * NN;
        const size_t base = (size_t)b * NN * NN;
        const int g = lane >> 2, q = lane & 3;

        #pragma unroll
        for (int mt = 0; mt < 2; mt++) {
            #pragma unroll
            for (int nt = 0; nt < 4; nt++) {
                const float* c = acc[mt][nt];
                const int lj = wx * 32 + nt * 8 + q * 2;
                const float2 cj0 = cj2[lj], cj1 = cj2[lj + 1];
                #pragma unroll
                for (int h = 0; h < 2; h++) {
                    const int li = wy * 32 + mt * 16 + g + h * 8;
                    const float2 ci = ci2[li];
                    float dx0 = ci.x - cj0.x, dy0 = ci.y - cj0.y;
                    float dx1 = ci.x - cj1.x, dy1 = ci.y - cj1.y;
                    float d20 = dx0 * dx0 + dy0 * dy0;
                    float d21 = dx1 * dx1 + dy1 * dy1;
                    bool s0 = diag && (li == lj);
                    bool s1 = diag && (li == lj + 1);
                    float av0 = s0 ? 0.0f : c[h * 2 + 0] * __expf(-sqrtf(d20));
                    float av1 = s1 ? 0.0f : c[h * 2 + 1] * __expf(-sqrtf(d21));
                    float sv0 = (!s0 && d20 < 1.0f) ? 1.0f : 0.0f;
                    float sv1 = (!s1 && d21 < 1.0f) ? 1.0f : 0.0f;
                    size_t ro = base + (size_t)(iBase + li) * NN + jBase + lj;
                    *reinterpret_cast<float2*>(outA + ro) = make_float2(av0, av1);
                    *reinterpret_cast<float2*>(outS + ro) = make_float2(sv0, sv1);
                    if (!diag) {
                        avt[(size_t)lj * AVT_S + li]       = av0;
                        avt[(size_t)(lj + 1) * AVT_S + li] = av1;
                    }
                }
            }
        }
    }

    // mirror pass
    if (!diag) {
        __syncthreads();
        const float* avt = reinterpret_cast<const float*>(sm + OFF_AVT);
        const float2* cj2 = reinterpret_cast<const float2*>(sm + OFF_CJ);
        const float4* ci4 = reinterpret_cast<const float4*>(sm + OFF_CI);
        float* outA = out;
        float* outS = out + (size_t)NB * NN * NN;
        const size_t base = (size_t)b * NN * NN;

        #pragma unroll
        for (int it = 0; it < 8; it++) {
            const int r = wid * 8 + it;     // local j row
            float4 av4 = *reinterpret_cast<const float4*>(avt + (size_t)r * AVT_S + lane * 4);
            float2 cj = cj2[r];
            float4 p0 = ci4[lane * 2], p1 = ci4[lane * 2 + 1];
            float d0x = cj.x - p0.x, d0y = cj.y - p0.y;
            float d1x = cj.x - p0.z, d1y = cj.y - p0.w;
            float d2x = cj.x - p1.x, d2y = cj.y - p1.y;
            float d3x = cj.x - p1.z, d3y = cj.y - p1.w;
            float4 sv4;
            sv4.x = (d0x * d0x + d0y * d0y < 1.0f) ? 1.0f : 0.0f;
            sv4.y = (d1x * d1x + d1y * d1y < 1.0f) ? 1.0f : 0.0f;
            sv4.z = (d2x * d2x + d2y * d2y < 1.0f) ? 1.0f : 0.0f;
            sv4.w = (d3x * d3x + d3y * d3y < 1.0f) ? 1.0f : 0.0f;
            size_t ro = base + (size_t)(jBase + r) * NN + iBase + lane * 4;
            *reinterpret_cast<float4*>(outA + ro) = av4;
            *reinterpret_cast<float4*>(outS + ro) = sv4;
        }
    }
}

extern "C" void kernel_launch(void* const* d_in, const int* in_sizes, int n_in,
                              void* d_out, int out_size) {
    (void)in_sizes; (void)n_in; (void)out_size;
    const float* fea   = (const float*)d_in[0];
    const float* coord = (const float*)d_in[1];
    float* out = (float*)d_out;

    prep_kernel<<<NB * NN / 8, 256>>>(fea);

    cudaFuncSetAttribute(adj_mma_kernel, cudaFuncAttributeMaxDynamicSharedMemorySize, SMEM_TOTAL);
    adj_mma_kernel<<<NB * 10, 512, SMEM_TOTAL>>>(coord, out);
}